// round 1
// baseline (speedup 1.0000x reference)
#include <cuda_runtime.h>
#include <math.h>

#define Bn 64
#define Nn 1024
#define Dn 64
#define ROWS 32
#define KBLK 128
#define THREADS 256

// XOR swizzle for a [rows][64] float tile: element (c, d) -> physical float index.
// Keeps 4-float groups contiguous (LDS.128-friendly) and spreads columns across banks.
__device__ __forceinline__ int swz(int c, int d) {
    return c * 64 + ((((d >> 2) ^ (c & 15)) << 2) | (d & 3));
}

__global__ __launch_bounds__(THREADS, 1)
void sdpa_sem_kernel(const float* __restrict__ q,
                     const float* __restrict__ k,
                     const float* __restrict__ v,
                     const float* __restrict__ qs,
                     const float* __restrict__ ks,
                     float* __restrict__ out,        // [B, N, D]
                     float* __restrict__ attn,       // [B, N, N]
                     float* __restrict__ score_out)  // [B, N, N]
{
    extern __shared__ float sm[];
    float* qf  = sm;                    // 32*64   = 2048 floats
    float* sc  = sm + ROWS * Dn;        // 32*1024 = 32768 floats
    float* buf = sc + ROWS * Nn;        // 128*64  = 8192 floats (swizzled tile)

    const int b    = blockIdx.y;
    const int row0 = blockIdx.x * ROWS;
    const int tid  = threadIdx.x;
    const int tcol = tid & 31;   // 0..31
    const int trow = tid >> 5;   // 0..7

    const size_t bND = (size_t)b * Nn * Dn;
    const size_t bNN = (size_t)b * Nn * Nn;

    // ---------------- Phase 1: qf = q + q_sem for our 32 rows ----------------
    {
        const float* qp  = q  + bND + (size_t)row0 * Dn;
        const float* qsp = qs + bND + (size_t)row0 * Dn;
        #pragma unroll
        for (int i = tid * 4; i < ROWS * Dn; i += THREADS * 4) {
            float4 a = *(const float4*)(qp  + i);
            float4 s = *(const float4*)(qsp + i);
            a.x += s.x; a.y += s.y; a.z += s.z; a.w += s.w;
            *(float4*)(qf + i) = a;
        }
    }

    // ---------------- Phase 2: scores = qf @ kf^T / 8 ----------------
    for (int kb = 0; kb < Nn / KBLK; kb++) {
        const int kbase = kb * KBLK;

        __syncthreads();  // buf reuse protection (and phase-1 qf on first iter)
        // load kf = k + k_sem tile [128 x 64] into swizzled buf
        {
            const float* kp  = k  + bND + (size_t)kbase * Dn;
            const float* ksp = ks + bND + (size_t)kbase * Dn;
            #pragma unroll
            for (int i = tid * 4; i < KBLK * Dn; i += THREADS * 4) {
                int c = i >> 6, d = i & 63;
                float4 a = *(const float4*)(kp  + i);
                float4 s = *(const float4*)(ksp + i);
                a.x += s.x; a.y += s.y; a.z += s.z; a.w += s.w;
                *(float4*)(buf + swz(c, d)) = a;  // group stays contiguous
            }
        }
        __syncthreads();

        // 4x4 microtile: rows trow*4+j, cols (local) tcol + 32*i
        float acc[4][4];
        #pragma unroll
        for (int j = 0; j < 4; j++)
            #pragma unroll
            for (int i = 0; i < 4; i++) acc[j][i] = 0.0f;

        #pragma unroll
        for (int d = 0; d < Dn; d += 4) {
            float4 a0 = *(const float4*)(qf + (trow * 4 + 0) * Dn + d);
            float4 a1 = *(const float4*)(qf + (trow * 4 + 1) * Dn + d);
            float4 a2 = *(const float4*)(qf + (trow * 4 + 2) * Dn + d);
            float4 a3 = *(const float4*)(qf + (trow * 4 + 3) * Dn + d);
            float4 b0 = *(const float4*)(buf + swz(tcol +  0, d));
            float4 b1 = *(const float4*)(buf + swz(tcol + 32, d));
            float4 b2 = *(const float4*)(buf + swz(tcol + 64, d));
            float4 b3 = *(const float4*)(buf + swz(tcol + 96, d));

            float4 aa[4] = {a0, a1, a2, a3};
            float4 bb[4] = {b0, b1, b2, b3};
            #pragma unroll
            for (int j = 0; j < 4; j++)
                #pragma unroll
                for (int i = 0; i < 4; i++) {
                    acc[j][i] = fmaf(aa[j].x, bb[i].x, acc[j][i]);
                    acc[j][i] = fmaf(aa[j].y, bb[i].y, acc[j][i]);
                    acc[j][i] = fmaf(aa[j].z, bb[i].z, acc[j][i]);
                    acc[j][i] = fmaf(aa[j].w, bb[i].w, acc[j][i]);
                }
        }

        // write scaled scores to smem + attn_score gmem
        #pragma unroll
        for (int j = 0; j < 4; j++) {
            const int r = trow * 4 + j;
            float* srow = sc + r * Nn + kbase;
            float* grow = score_out + bNN + (size_t)(row0 + r) * Nn + kbase;
            #pragma unroll
            for (int i = 0; i < 4; i++) {
                float s = acc[j][i] * 0.125f;
                srow[tcol + 32 * i] = s;
                grow[tcol + 32 * i] = s;
            }
        }
    }
    __syncthreads();

    // ---------------- Phase 3: softmax rows (1 warp per 4 rows) ----------------
    {
        const int w    = tid >> 5;
        const int lane = tid & 31;
        for (int j = 0; j < 4; j++) {
            const int r = w * 4 + j;
            float* srow = sc + r * Nn;
            float4 vals[8];
            float m = -INFINITY;
            #pragma unroll
            for (int i = 0; i < 8; i++) {
                vals[i] = *(const float4*)(srow + 4 * (lane + 32 * i));
                m = fmaxf(m, fmaxf(fmaxf(vals[i].x, vals[i].y),
                                   fmaxf(vals[i].z, vals[i].w)));
            }
            #pragma unroll
            for (int off = 16; off; off >>= 1)
                m = fmaxf(m, __shfl_xor_sync(0xffffffffu, m, off));

            float sum = 0.0f;
            #pragma unroll
            for (int i = 0; i < 8; i++) {
                vals[i].x = __expf(vals[i].x - m);
                vals[i].y = __expf(vals[i].y - m);
                vals[i].z = __expf(vals[i].z - m);
                vals[i].w = __expf(vals[i].w - m);
                sum += vals[i].x + vals[i].y + vals[i].z + vals[i].w;
            }
            #pragma unroll
            for (int off = 16; off; off >>= 1)
                sum += __shfl_xor_sync(0xffffffffu, sum, off);
            const float inv = 1.0f / sum;

            float* garow = attn + bNN + (size_t)(row0 + r) * Nn;
            #pragma unroll
            for (int i = 0; i < 8; i++) {
                float4 p;
                p.x = vals[i].x * inv; p.y = vals[i].y * inv;
                p.z = vals[i].z * inv; p.w = vals[i].w * inv;
                *(float4*)(srow  + 4 * (lane + 32 * i)) = p;   // keep P in smem
                *(float4*)(garow + 4 * (lane + 32 * i)) = p;   // attn out
            }
        }
    }

    // ---------------- Phase 4: out = P @ V ----------------
    float oacc[4][2];
    #pragma unroll
    for (int j = 0; j < 4; j++) { oacc[j][0] = 0.0f; oacc[j][1] = 0.0f; }

    for (int kb = 0; kb < Nn / KBLK; kb++) {
        const int kbase = kb * KBLK;
        __syncthreads();
        // load V tile [128 keys x 64 dims] into swizzled buf
        {
            const float* vp = v + bND + (size_t)kbase * Dn;
            #pragma unroll
            for (int i = tid * 4; i < KBLK * Dn; i += THREADS * 4) {
                int c = i >> 6, d = i & 63;
                float4 a = *(const float4*)(vp + i);
                *(float4*)(buf + swz(c, d)) = a;
            }
        }
        __syncthreads();

        const int c0 = tcol;
        const int c1 = tcol + 32;
        #pragma unroll 4
        for (int kk = 0; kk < KBLK; kk += 4) {
            float4 p0 = *(const float4*)(sc + (trow * 4 + 0) * Nn + kbase + kk);
            float4 p1 = *(const float4*)(sc + (trow * 4 + 1) * Nn + kbase + kk);
            float4 p2 = *(const float4*)(sc + (trow * 4 + 2) * Nn + kbase + kk);
            float4 p3 = *(const float4*)(sc + (trow * 4 + 3) * Nn + kbase + kk);

            float4 pp[4] = {p0, p1, p2, p3};
            #pragma unroll
            for (int t = 0; t < 4; t++) {
                const int kr = kk + t;
                float v0 = buf[swz(kr, c0)];
                float v1 = buf[swz(kr, c1)];
                float pe;
                #pragma unroll
                for (int j = 0; j < 4; j++) {
                    pe = (t == 0) ? pp[j].x : (t == 1) ? pp[j].y
                       : (t == 2) ? pp[j].z : pp[j].w;
                    oacc[j][0] = fmaf(pe, v0, oacc[j][0]);
                    oacc[j][1] = fmaf(pe, v1, oacc[j][1]);
                }
            }
        }
    }

    // write output
    #pragma unroll
    for (int j = 0; j < 4; j++) {
        const int r = row0 + trow * 4 + j;
        float* orow = out + bND + (size_t)r * Dn;
        orow[tcol]      = oacc[j][0];
        orow[tcol + 32] = oacc[j][1];
    }
}

extern "C" void kernel_launch(void* const* d_in, const int* in_sizes, int n_in,
                              void* d_out, int out_size) {
    const float* q  = (const float*)d_in[0];
    const float* k  = (const float*)d_in[1];
    const float* v  = (const float*)d_in[2];
    const float* qs = (const float*)d_in[3];
    const float* ks = (const float*)d_in[4];

    float* out   = (float*)d_out;                          // [64,1024,64]
    float* attn  = out  + (size_t)Bn * Nn * Dn;            // [64,1024,1024]
    float* score = attn + (size_t)Bn * Nn * Nn;            // [64,1024,1024]

    const int smem_bytes = (ROWS * Dn + ROWS * Nn + KBLK * Dn) * (int)sizeof(float);
    cudaFuncSetAttribute(sdpa_sem_kernel,
                         cudaFuncAttributeMaxDynamicSharedMemorySize, smem_bytes);

    dim3 grid(Nn / ROWS, Bn);
    sdpa_sem_kernel<<<grid, THREADS, smem_bytes>>>(q, k, v, qs, ks, out, attn, score);
}